// round 1
// baseline (speedup 1.0000x reference)
#include <cuda_runtime.h>
#include <cuda_bf16.h>

// Problem shape (fixed by the dataset):
//   x:             [8, 4096, 256]  -> N = 32768 rows, IN = 256
//   base_weight:   [256, 256]         (OUT, IN)
//   spline_weight: [256, 256, 8]      (OUT, IN, COEF)
//   out:           [32768, 256] fp32
//
// out[n,o] = sum_i silu(x[n,i]) * baseW[o,i]
//          + sum_{i,c} B_c(x[n,i]) * splineW[o,i,c]
// i.e. a GEMM with K = 256*9 = 2304, where each input feature contributes a
// 9-vector [silu(x), B_0..B_7(x)].

#define N_IN   256
#define N_OUT  256
#define COEF   8
#define KTOT   (N_IN * 9)          // 2304

#define TM 64
#define TN 64
#define CF 8                        // features per K-chunk
#define KC (CF * 9)                 // 72 K-steps per chunk
#define NCHUNK (N_IN / CF)          // 32
#define AS_STRIDE 68                // padded (mult of 4 for float4, conflict-free)
#define BS_STRIDE 68

// K-major repacked weights: Wt[k][o], k = i*9 + j (j==0 -> base, j>=1 -> spline c=j-1)
__device__ float g_Wt[KTOT * N_OUT];

// ---------------------------------------------------------------------------
// Weight repack: interleave base/spline into K-major [2304, 256]
// ---------------------------------------------------------------------------
__global__ void repack_weights_kernel(const float* __restrict__ baseW,
                                      const float* __restrict__ splineW) {
    int idx = blockIdx.x * blockDim.x + threadIdx.x;
    if (idx >= KTOT * N_OUT) return;
    int o = idx % N_OUT;
    int k = idx / N_OUT;
    int i = k / 9;
    int j = k % 9;
    float v = (j == 0) ? baseW[o * N_IN + i]
                       : splineW[o * (N_IN * COEF) + i * COEF + (j - 1)];
    g_Wt[k * N_OUT + o] = v;   // coalesced writes
}

// ---------------------------------------------------------------------------
// Cubic B-spline basis on the uniform KAN grid:
//   grid[j] = -2.2 + j*0.4,  j = 0..11  (G=5, k=3, h = 2/G = 0.4)
// Cox-de-Boor recursion exactly matching the reference.
// ---------------------------------------------------------------------------
__device__ __forceinline__ void compute_bases(float x, float b[8]) {
    const float h = 0.4f;
    float t[11];
#pragma unroll
    for (int i = 0; i < 11; i++) {
        float gl = -2.2f + (float)i * h;
        float gr = gl + h;
        t[i] = (x >= gl && x < gr) ? 1.0f : 0.0f;
    }
    // k = 1: denom = h
#pragma unroll
    for (int i = 0; i < 10; i++) {
        float gi = -2.2f + (float)i * h;
        t[i] = (x - gi) * 2.5f * t[i] + ((gi + 2.0f * h) - x) * 2.5f * t[i + 1];
    }
    // k = 2: denom = 2h
#pragma unroll
    for (int i = 0; i < 9; i++) {
        float gi = -2.2f + (float)i * h;
        t[i] = (x - gi) * 1.25f * t[i] + ((gi + 3.0f * h) - x) * 1.25f * t[i + 1];
    }
    // k = 3: denom = 3h
#pragma unroll
    for (int i = 0; i < 8; i++) {
        float gi = -2.2f + (float)i * h;
        b[i] = (x - gi) * (2.5f / 3.0f) * t[i]
             + ((gi + 4.0f * h) - x) * (2.5f / 3.0f) * t[i + 1];
    }
}

// ---------------------------------------------------------------------------
// Fused KAN GEMM: 64x64 tile per CTA, 4x4 per thread, fp32 FFMA.
// A-tile (activations) is generated on the fly from x.
// ---------------------------------------------------------------------------
__global__ __launch_bounds__(256, 2)
void kan_gemm_kernel(const float* __restrict__ x,
                     float* __restrict__ out,
                     int n_rows) {
    __shared__ float As[KC * AS_STRIDE];
    __shared__ float Bs[KC * BS_STRIDE];

    const int tid  = threadIdx.x;
    const int row0 = blockIdx.x * TM;
    const int col0 = blockIdx.y * TN;

    const int tr = tid / 16;        // 0..15
    const int tc = tid % 16;        // 0..15
    const int r0 = tr * 4;
    const int c0 = tc * 4;

    float acc[4][4];
#pragma unroll
    for (int a = 0; a < 4; a++)
#pragma unroll
        for (int b = 0; b < 4; b++) acc[a][b] = 0.0f;

    for (int ch = 0; ch < NCHUNK; ch++) {
        const int i0 = ch * CF;
        __syncthreads();   // previous chunk's reads done before overwrite

        // --- stage A: load x tile, compute silu + 8 spline bases ---
        // 64 rows x 8 feats = 512 elements, 2 per thread
#pragma unroll
        for (int e = tid; e < TM * CF; e += 256) {
            int f = e % CF;
            int r = e / CF;
            float xv = x[(size_t)(row0 + r) * N_IN + i0 + f];
            float sig = 1.0f / (1.0f + __expf(-xv));
            As[(f * 9 + 0) * AS_STRIDE + r] = xv * sig;
            float bb[8];
            compute_bases(xv, bb);
#pragma unroll
            for (int j = 0; j < 8; j++)
                As[(f * 9 + 1 + j) * AS_STRIDE + r] = bb[j];
        }

        // --- stage B: load K-major weights (coalesced) ---
        // 72 x 64 = 4608 floats, 18 per thread
#pragma unroll
        for (int e = tid; e < KC * TN; e += 256) {
            int o = e % TN;
            int k = e / TN;
            Bs[k * BS_STRIDE + o] = g_Wt[(size_t)(i0 * 9 + k) * N_OUT + col0 + o];
        }
        __syncthreads();

        // --- compute: 72 K-steps, 16 FFMA each ---
#pragma unroll 4
        for (int k = 0; k < KC; k++) {
            float4 av = *reinterpret_cast<const float4*>(&As[k * AS_STRIDE + r0]);
            float4 bv = *reinterpret_cast<const float4*>(&Bs[k * BS_STRIDE + c0]);
            acc[0][0] += av.x * bv.x; acc[0][1] += av.x * bv.y;
            acc[0][2] += av.x * bv.z; acc[0][3] += av.x * bv.w;
            acc[1][0] += av.y * bv.x; acc[1][1] += av.y * bv.y;
            acc[1][2] += av.y * bv.z; acc[1][3] += av.y * bv.w;
            acc[2][0] += av.z * bv.x; acc[2][1] += av.z * bv.y;
            acc[2][2] += av.z * bv.z; acc[2][3] += av.z * bv.w;
            acc[3][0] += av.w * bv.x; acc[3][1] += av.w * bv.y;
            acc[3][2] += av.w * bv.z; acc[3][3] += av.w * bv.w;
        }
    }

    // --- epilogue: vectorized stores ---
#pragma unroll
    for (int rr = 0; rr < 4; rr++) {
        float4 v = make_float4(acc[rr][0], acc[rr][1], acc[rr][2], acc[rr][3]);
        *reinterpret_cast<float4*>(
            &out[(size_t)(row0 + r0 + rr) * N_OUT + col0 + c0]) = v;
    }
}

// ---------------------------------------------------------------------------
// kernel_launch
// inputs (metadata order): x [8,4096,256] f32, base_weight [256,256] f32,
//                          spline_weight [256,256,8] f32; out f32 [8,4096,256]
// ---------------------------------------------------------------------------
extern "C" void kernel_launch(void* const* d_in, const int* in_sizes, int n_in,
                              void* d_out, int out_size) {
    const float* x       = (const float*)d_in[0];
    const float* baseW   = (const float*)d_in[1];
    const float* splineW = (const float*)d_in[2];
    float* out           = (float*)d_out;

    const int n_rows = in_sizes[0] / N_IN;   // 32768

    // 1) repack weights into K-major layout (runs every launch; deterministic)
    {
        int total = KTOT * N_OUT;
        repack_weights_kernel<<<(total + 255) / 256, 256>>>(baseW, splineW);
    }

    // 2) fused KAN GEMM
    {
        dim3 grid(n_rows / TM, N_OUT / TN);   // (512, 4)
        kan_gemm_kernel<<<grid, 256>>>(x, out, n_rows);
    }
}

// round 2
// speedup vs baseline: 1.0006x; 1.0006x over previous
#include <cuda_runtime.h>
#include <cuda_bf16.h>

// Problem shape (fixed by the dataset):
//   x:             [8, 4096, 256]  -> N = 32768 rows, IN = 256
//   base_weight:   [256, 256]         (OUT, IN)
//   spline_weight: [256, 256, 8]      (OUT, IN, COEF)
//   out:           [32768, 256] fp32
//
// out[n,o] = sum_i silu(x[n,i]) * baseW[o,i]
//          + sum_{i,c} B_c(x[n,i]) * splineW[o,i,c]
// i.e. a GEMM with K = 256*9 = 2304, where each input feature contributes a
// 9-vector [silu(x), B_0..B_7(x)].

#define N_IN   256
#define N_OUT  256
#define COEF   8
#define KTOT   (N_IN * 9)          // 2304

#define TM 64
#define TN 64
#define CF 8                        // features per K-chunk
#define KC (CF * 9)                 // 72 K-steps per chunk
#define NCHUNK (N_IN / CF)          // 32
#define AS_STRIDE 68                // padded (mult of 4 for float4, conflict-free)
#define BS_STRIDE 68

// K-major repacked weights: Wt[k][o], k = i*9 + j (j==0 -> base, j>=1 -> spline c=j-1)
__device__ float g_Wt[KTOT * N_OUT];

// ---------------------------------------------------------------------------
// Weight repack: interleave base/spline into K-major [2304, 256]
// ---------------------------------------------------------------------------
__global__ void repack_weights_kernel(const float* __restrict__ baseW,
                                      const float* __restrict__ splineW) {
    int idx = blockIdx.x * blockDim.x + threadIdx.x;
    if (idx >= KTOT * N_OUT) return;
    int o = idx % N_OUT;
    int k = idx / N_OUT;
    int i = k / 9;
    int j = k % 9;
    float v = (j == 0) ? baseW[o * N_IN + i]
                       : splineW[o * (N_IN * COEF) + i * COEF + (j - 1)];
    g_Wt[k * N_OUT + o] = v;   // coalesced writes
}

// ---------------------------------------------------------------------------
// Cubic B-spline basis on the uniform KAN grid:
//   grid[j] = -2.2 + j*0.4,  j = 0..11  (G=5, k=3, h = 2/G = 0.4)
// Cox-de-Boor recursion exactly matching the reference.
// ---------------------------------------------------------------------------
__device__ __forceinline__ void compute_bases(float x, float b[8]) {
    const float h = 0.4f;
    float t[11];
#pragma unroll
    for (int i = 0; i < 11; i++) {
        float gl = -2.2f + (float)i * h;
        float gr = gl + h;
        t[i] = (x >= gl && x < gr) ? 1.0f : 0.0f;
    }
    // k = 1: denom = h
#pragma unroll
    for (int i = 0; i < 10; i++) {
        float gi = -2.2f + (float)i * h;
        t[i] = (x - gi) * 2.5f * t[i] + ((gi + 2.0f * h) - x) * 2.5f * t[i + 1];
    }
    // k = 2: denom = 2h
#pragma unroll
    for (int i = 0; i < 9; i++) {
        float gi = -2.2f + (float)i * h;
        t[i] = (x - gi) * 1.25f * t[i] + ((gi + 3.0f * h) - x) * 1.25f * t[i + 1];
    }
    // k = 3: denom = 3h
#pragma unroll
    for (int i = 0; i < 8; i++) {
        float gi = -2.2f + (float)i * h;
        b[i] = (x - gi) * (2.5f / 3.0f) * t[i]
             + ((gi + 4.0f * h) - x) * (2.5f / 3.0f) * t[i + 1];
    }
}

// ---------------------------------------------------------------------------
// Fused KAN GEMM: 64x64 tile per CTA, 4x4 per thread, fp32 FFMA.
// A-tile (activations) is generated on the fly from x.
// ---------------------------------------------------------------------------
__global__ __launch_bounds__(256, 2)
void kan_gemm_kernel(const float* __restrict__ x,
                     float* __restrict__ out,
                     int n_rows) {
    __shared__ float As[KC * AS_STRIDE];
    __shared__ float Bs[KC * BS_STRIDE];

    const int tid  = threadIdx.x;
    const int row0 = blockIdx.x * TM;
    const int col0 = blockIdx.y * TN;

    const int tr = tid / 16;        // 0..15
    const int tc = tid % 16;        // 0..15
    const int r0 = tr * 4;
    const int c0 = tc * 4;

    float acc[4][4];
#pragma unroll
    for (int a = 0; a < 4; a++)
#pragma unroll
        for (int b = 0; b < 4; b++) acc[a][b] = 0.0f;

    for (int ch = 0; ch < NCHUNK; ch++) {
        const int i0 = ch * CF;
        __syncthreads();   // previous chunk's reads done before overwrite

        // --- stage A: load x tile, compute silu + 8 spline bases ---
        // 64 rows x 8 feats = 512 elements, 2 per thread
#pragma unroll
        for (int e = tid; e < TM * CF; e += 256) {
            int f = e % CF;
            int r = e / CF;
            float xv = x[(size_t)(row0 + r) * N_IN + i0 + f];
            float sig = 1.0f / (1.0f + __expf(-xv));
            As[(f * 9 + 0) * AS_STRIDE + r] = xv * sig;
            float bb[8];
            compute_bases(xv, bb);
#pragma unroll
            for (int j = 0; j < 8; j++)
                As[(f * 9 + 1 + j) * AS_STRIDE + r] = bb[j];
        }

        // --- stage B: load K-major weights (coalesced) ---
        // 72 x 64 = 4608 floats, 18 per thread
#pragma unroll
        for (int e = tid; e < KC * TN; e += 256) {
            int o = e % TN;
            int k = e / TN;
            Bs[k * BS_STRIDE + o] = g_Wt[(size_t)(i0 * 9 + k) * N_OUT + col0 + o];
        }
        __syncthreads();

        // --- compute: 72 K-steps, 16 FFMA each ---
#pragma unroll 4
        for (int k = 0; k < KC; k++) {
            float4 av = *reinterpret_cast<const float4*>(&As[k * AS_STRIDE + r0]);
            float4 bv = *reinterpret_cast<const float4*>(&Bs[k * BS_STRIDE + c0]);
            acc[0][0] += av.x * bv.x; acc[0][1] += av.x * bv.y;
            acc[0][2] += av.x * bv.z; acc[0][3] += av.x * bv.w;
            acc[1][0] += av.y * bv.x; acc[1][1] += av.y * bv.y;
            acc[1][2] += av.y * bv.z; acc[1][3] += av.y * bv.w;
            acc[2][0] += av.z * bv.x; acc[2][1] += av.z * bv.y;
            acc[2][2] += av.z * bv.z; acc[2][3] += av.z * bv.w;
            acc[3][0] += av.w * bv.x; acc[3][1] += av.w * bv.y;
            acc[3][2] += av.w * bv.z; acc[3][3] += av.w * bv.w;
        }
    }

    // --- epilogue: vectorized stores ---
#pragma unroll
    for (int rr = 0; rr < 4; rr++) {
        float4 v = make_float4(acc[rr][0], acc[rr][1], acc[rr][2], acc[rr][3]);
        *reinterpret_cast<float4*>(
            &out[(size_t)(row0 + r0 + rr) * N_OUT + col0 + c0]) = v;
    }
}

// ---------------------------------------------------------------------------
// kernel_launch
// inputs (metadata order): x [8,4096,256] f32, base_weight [256,256] f32,
//                          spline_weight [256,256,8] f32; out f32 [8,4096,256]
// ---------------------------------------------------------------------------
extern "C" void kernel_launch(void* const* d_in, const int* in_sizes, int n_in,
                              void* d_out, int out_size) {
    const float* x       = (const float*)d_in[0];
    const float* baseW   = (const float*)d_in[1];
    const float* splineW = (const float*)d_in[2];
    float* out           = (float*)d_out;

    const int n_rows = in_sizes[0] / N_IN;   // 32768

    // 1) repack weights into K-major layout (runs every launch; deterministic)
    {
        int total = KTOT * N_OUT;
        repack_weights_kernel<<<(total + 255) / 256, 256>>>(baseW, splineW);
    }

    // 2) fused KAN GEMM
    {
        dim3 grid(n_rows / TM, N_OUT / TN);   // (512, 4)
        kan_gemm_kernel<<<grid, 256>>>(x, out, n_rows);
    }
}

// round 4
// speedup vs baseline: 4.3701x; 4.3674x over previous
#include <cuda_runtime.h>
#include <cuda_fp16.h>
#include <stdint.h>

// out[32768,256] = A[32768, K=2304] * Wt[K,256], fp16 operands, fp32 accum,
// via ldmatrix + mma.sync.m16n8k16 (portable: compiles for compute_100).
//
// K layout: k = 9*i + j; j=0: silu(x_i), j=1..8: cubic B-spline bases.
// CTA tile: 128 rows x 128 outs. Chunk: 16 features = 144 k = 9 k16 steps.
// A generated on the fly into SMEM; B (fp16 repack) staged with cp.async.
// Both SMEM tiles are [row][k] with 304-byte row stride (bank-conflict-free
// for ldmatrix wavefronts and STS.128: 76 words, 76 mod 32 = 12).

#define N_IN   256
#define KTOT   2304
#define CHUNKS 16
#define CK     144          // k per chunk
#define KSTEPS 9            // 144/16
#define ROWB   304          // smem row stride bytes (152 halves)
#define TBUF   (128 * ROWB) // one tile buffer: 38912 B
#define DYN_SMEM (4 * TBUF) // A0 A1 B0 B1 = 155648 B

__device__ __align__(128) __half g_Wh[N_IN * KTOT];   // [out][k] fp16

// ---- helpers --------------------------------------------------------------
__device__ __forceinline__ uint32_t smem_u32(const void* p) {
    uint32_t a;
    asm("{ .reg .u64 t; cvta.to.shared.u64 t, %1; cvt.u32.u64 %0, t; }" : "=r"(a) : "l"(p));
    return a;
}
__device__ __forceinline__ void cp16(uint32_t dst, const void* src) {
    asm volatile("cp.async.cg.shared.global [%0], [%1], 16;" :: "r"(dst), "l"(src) : "memory");
}
__device__ __forceinline__ void cp_commit() {
    asm volatile("cp.async.commit_group;" ::: "memory");
}
template <int N>
__device__ __forceinline__ void cp_wait() {
    asm volatile("cp.async.wait_group %0;" :: "n"(N) : "memory");
}
__device__ __forceinline__ void ldm_x4(uint32_t& r0, uint32_t& r1, uint32_t& r2, uint32_t& r3,
                                       uint32_t addr) {
    asm volatile("ldmatrix.sync.aligned.m8n8.x4.shared.b16 {%0,%1,%2,%3}, [%4];"
                 : "=r"(r0), "=r"(r1), "=r"(r2), "=r"(r3) : "r"(addr));
}
__device__ __forceinline__ void mma16816(float& c0, float& c1, float& c2, float& c3,
                                         uint32_t a0, uint32_t a1, uint32_t a2, uint32_t a3,
                                         uint32_t b0, uint32_t b1) {
    asm volatile(
        "mma.sync.aligned.m16n8k16.row.col.f32.f16.f16.f32 "
        "{%0,%1,%2,%3}, {%4,%5,%6,%7}, {%8,%9}, {%0,%1,%2,%3};"
        : "+f"(c0), "+f"(c1), "+f"(c2), "+f"(c3)
        : "r"(a0), "r"(a1), "r"(a2), "r"(a3), "r"(b0), "r"(b1));
}

// ---- cubic B-spline bases on grid -2.2 + 0.4j (validated round 1) ---------
__device__ __forceinline__ void compute_bases(float x, float b[8]) {
    const float h = 0.4f;
    float t[11];
#pragma unroll
    for (int i = 0; i < 11; i++) {
        float gl = -2.2f + i * h;
        t[i] = (x >= gl && x < gl + h) ? 1.0f : 0.0f;
    }
#pragma unroll
    for (int i = 0; i < 10; i++) {
        float gi = -2.2f + i * h;
        t[i] = (x - gi) * 2.5f * t[i] + ((gi + 2.f * h) - x) * 2.5f * t[i + 1];
    }
#pragma unroll
    for (int i = 0; i < 9; i++) {
        float gi = -2.2f + i * h;
        t[i] = (x - gi) * 1.25f * t[i] + ((gi + 3.f * h) - x) * 1.25f * t[i + 1];
    }
#pragma unroll
    for (int i = 0; i < 8; i++) {
        float gi = -2.2f + i * h;
        b[i] = (x - gi) * (2.5f / 3.f) * t[i] + ((gi + 4.f * h) - x) * (2.5f / 3.f) * t[i + 1];
    }
}

// ---- weight repack to fp16 [out][k] ---------------------------------------
__global__ void repack_kernel(const float* __restrict__ baseW,
                              const float* __restrict__ splineW) {
    int idx = blockIdx.x * blockDim.x + threadIdx.x;
    if (idx >= N_IN * KTOT) return;
    int o = idx / KTOT, k = idx % KTOT;
    int i = k / 9, j = k % 9;
    float v = (j == 0) ? baseW[o * N_IN + i] : splineW[o * (N_IN * 8) + i * 8 + (j - 1)];
    g_Wh[idx] = __float2half_rn(v);
}

// ---- main fused kernel ----------------------------------------------------
__global__ __launch_bounds__(256, 1)
void kan_hmma_kernel(const float* __restrict__ x, float* __restrict__ out) {
    extern __shared__ __align__(128) unsigned char dsm[];   // A0 A1 B0 B1
    const uint32_t sb = smem_u32(dsm);
    const int tid = threadIdx.x, wid = tid >> 5, lane = tid & 31;
    const int row0 = blockIdx.x * 128;
    const int ct   = blockIdx.y;              // output col tile (0/1)

    // A generation mapping: thread -> (row, feature-half)
    const int grow = tid & 127;               // 0..127
    const int gfh  = tid >> 7;                // 0/1 -> features 8*gfh..8*gfh+7
    const float* xrow = x + (size_t)(row0 + grow) * N_IN;

    // B cp.async mapping: 128 rows x 18 segs of 16B; 9 per thread
    // seg e: n = e/18, s = e%18
    // warp-tile mapping
    const int wm = wid & 1;                   // 0/1 -> rows 0-63 / 64-127
    const int wn = wid >> 1;                  // 0..3 -> cols wn*32

    // ldmatrix per-thread address components
    const uint32_t a_off = (uint32_t)(wm * 64 + (lane & 15)) * ROWB + ((lane >> 4) << 3) * 2;
    const uint32_t b_off = (uint32_t)(wn * 32 + ((lane >> 4) << 3) + (lane & 7)) * ROWB
                         + (((lane >> 3) & 1) << 3) * 2;

    float C[4][4][4];                          // [mt][nt8][frag]
#pragma unroll
    for (int a = 0; a < 4; a++)
#pragma unroll
        for (int b = 0; b < 4; b++)
#pragma unroll
            for (int c = 0; c < 4; c++) C[a][b][c] = 0.f;

    // ---- A generator (chunk c -> buffer base byte offset within dsm) ----
    auto genA = [&](int c, uint32_t abyte) {
        float4 xa = *reinterpret_cast<const float4*>(xrow + c * 16 + gfh * 8);
        float4 xb = *reinterpret_cast<const float4*>(xrow + c * 16 + gfh * 8 + 4);
        float xv[8] = {xa.x, xa.y, xa.z, xa.w, xb.x, xb.y, xb.z, xb.w};
        uint32_t pk[36];
#pragma unroll
        for (int i = 0; i < 36; i++) pk[i] = 0u;
#pragma unroll
        for (int f = 0; f < 8; f++) {
            float v = xv[f];
            float sil = v / (1.f + __expf(-v));
            float bs[8];
            compute_bases(v, bs);
            unsigned short hh[9];
            hh[0] = __half_as_ushort(__float2half_rn(sil));
#pragma unroll
            for (int j = 0; j < 8; j++) hh[j + 1] = __half_as_ushort(__float2half_rn(bs[j]));
#pragma unroll
            for (int j = 0; j < 9; j++) {
                int pos = 9 * f + j;
                pk[pos >> 1] |= (uint32_t)hh[j] << ((pos & 1) * 16);
            }
        }
        unsigned char* dst = dsm + abyte + (uint32_t)grow * ROWB + (uint32_t)gfh * 144;
#pragma unroll
        for (int q = 0; q < 9; q++) {
            uint4 v = make_uint4(pk[4 * q], pk[4 * q + 1], pk[4 * q + 2], pk[4 * q + 3]);
            *reinterpret_cast<uint4*>(dst + q * 16) = v;
        }
    };

    // ---- B stage via cp.async ----
    auto issueB = [&](int c, uint32_t bbyte) {
        const __half* src0 = g_Wh + (size_t)(ct * 128) * KTOT + c * CK;
#pragma unroll
        for (int s = 0; s < 9; s++) {
            int e = tid + 256 * s;            // 0..2303
            int n = e / 18, seg = e % 18;
            cp16(sb + bbyte + (uint32_t)n * ROWB + seg * 16,
                 src0 + (size_t)n * KTOT + seg * 8);
        }
        cp_commit();
    };

    // ---- prologue ----
    genA(0, 0);
    issueB(0, 2 * TBUF);
    issueB(1, 3 * TBUF);
    cp_wait<1>();
    __syncthreads();

    // ---- main loop ----
    for (int c = 0; c < CHUNKS; c++) {
        const int buf = c & 1;
        const uint32_t abase = sb + buf * TBUF;
        const uint32_t bbase = sb + (2 + buf) * TBUF;

#pragma unroll
        for (int s = 0; s < KSTEPS; s++) {
            const uint32_t kb = (uint32_t)(s * 16) * 2;   // byte offset of k0
            uint32_t A[4][4], B[2][4];
#pragma unroll
            for (int mt = 0; mt < 4; mt++)
                ldm_x4(A[mt][0], A[mt][1], A[mt][2], A[mt][3],
                       abase + a_off + (uint32_t)mt * (16 * ROWB) + kb);
#pragma unroll
            for (int nt = 0; nt < 2; nt++)
                ldm_x4(B[nt][0], B[nt][1], B[nt][2], B[nt][3],
                       bbase + b_off + (uint32_t)nt * (16 * ROWB) + kb);
#pragma unroll
            for (int mt = 0; mt < 4; mt++)
#pragma unroll
                for (int nt = 0; nt < 2; nt++) {
                    mma16816(C[mt][2 * nt][0], C[mt][2 * nt][1],
                             C[mt][2 * nt][2], C[mt][2 * nt][3],
                             A[mt][0], A[mt][1], A[mt][2], A[mt][3],
                             B[nt][0], B[nt][1]);
                    mma16816(C[mt][2 * nt + 1][0], C[mt][2 * nt + 1][1],
                             C[mt][2 * nt + 1][2], C[mt][2 * nt + 1][3],
                             A[mt][0], A[mt][1], A[mt][2], A[mt][3],
                             B[nt][2], B[nt][3]);
                }
        }

        if (c + 1 < CHUNKS) genA(c + 1, (uint32_t)(buf ^ 1) * TBUF);
        __syncthreads();
        if (c + 2 < CHUNKS) issueB(c + 2, (uint32_t)(2 + buf) * TBUF);
        if (c + 2 < CHUNKS) cp_wait<1>(); else cp_wait<0>();
        __syncthreads();
    }

    // ---- epilogue: C frag -> gmem ----
    const int crow = lane >> 2, ccol = (lane & 3) * 2;
#pragma unroll
    for (int mt = 0; mt < 4; mt++) {
        int r = row0 + wm * 64 + mt * 16 + crow;
#pragma unroll
        for (int nt8 = 0; nt8 < 4; nt8++) {
            int cc = ct * 128 + wn * 32 + nt8 * 8 + ccol;
            *reinterpret_cast<float2*>(out + (size_t)r * 256 + cc) =
                make_float2(C[mt][nt8][0], C[mt][nt8][1]);
            *reinterpret_cast<float2*>(out + (size_t)(r + 8) * 256 + cc) =
                make_float2(C[mt][nt8][2], C[mt][nt8][3]);
        }
    }
}

// ---- launch ---------------------------------------------------------------
extern "C" void kernel_launch(void* const* d_in, const int* in_sizes, int n_in,
                              void* d_out, int out_size) {
    const float* x       = (const float*)d_in[0];
    const float* baseW   = (const float*)d_in[1];
    const float* splineW = (const float*)d_in[2];
    float* out           = (float*)d_out;
    const int n_rows = in_sizes[0] / N_IN;            // 32768

    repack_kernel<<<(N_IN * KTOT + 255) / 256, 256>>>(baseW, splineW);

    cudaFuncSetAttribute(kan_hmma_kernel, cudaFuncAttributeMaxDynamicSharedMemorySize, DYN_SMEM);
    dim3 grid(n_rows / 128, 2);
    kan_hmma_kernel<<<grid, 256, DYN_SMEM>>>(x, out);
}